// round 1
// baseline (speedup 1.0000x reference)
#include <cuda_runtime.h>
#include <math.h>

#define BSZ 32
#define TT  50
#define PP  3
#define TP  150      // TT*PP
#define NH  4
#define KD  88       // 44 keypoints * 2 coords

// Scratch: per-(b,i) partial sums (device global — no allocation allowed)
__device__ double g_partial[BSZ * TP];

// One block per (b, i) row. blockDim = 160.
__global__ void smooth_row_kernel(const int* __restrict__ idx,
                                  const float* __restrict__ kp,
                                  const float* __restrict__ attn)
{
    const int bi  = blockIdx.x;
    const int b   = bi / TP;
    const int i   = bi % TP;
    const int tid = threadIdx.x;

    __shared__ float s_kpi[KD];
    __shared__ float s_d[TP];       // d(i,j) * idx_j
    __shared__ float s_e[NH][9];    // per-head normalized softmax weights (allowed cols)

    const float* kpb = kp + (size_t)b * TP * KD;
    const int idx_i  = idx[b * TP + i];

    if (tid < KD) s_kpi[tid] = kpb[(size_t)i * KD + tid];
    __syncthreads();

    const int fi = i / PP;

    if (fi < TT - 1) {
        // ---- sparse row: allowed frames [max(fi-1,0), min(fi+1,48)] ----
        const int lo  = (fi - 1 > 0) ? (fi - 1) : 0;
        const int hi  = (fi + 1 < TT - 2) ? (fi + 1) : (TT - 2);
        const int jlo = lo * PP;
        const int cnt = (hi - lo + 1) * PP;   // 6 or 9

        if (tid < cnt) {
            const int j = jlo + tid;
            const float* kpj = kpb + (size_t)j * KD;
            float d = 0.0f;
            #pragma unroll
            for (int k = 0; k < KD; k++) d += fabsf(kpj[k] - s_kpi[k]);
            s_d[tid] = d * (float)idx[b * TP + j];
        }
        // heads handled by threads 32..35 (separate warp, runs concurrently)
        if (tid >= 32 && tid < 32 + NH) {
            const int h = tid - 32;
            const float* arow = attn + ((((size_t)b * NH + h) * TP + i) * TP) + jlo;
            float m = -1e30f;
            float a[9];
            for (int j = 0; j < cnt; j++) { a[j] = arow[j]; m = fmaxf(m, a[j]); }
            float Z = 0.0f;
            float e[9];
            for (int j = 0; j < cnt; j++) { e[j] = expf(a[j] - m); Z += e[j]; }
            const float invZ = 1.0f / Z;
            for (int j = 0; j < cnt; j++) s_e[h][j] = e[j] * invZ;
        }
        __syncthreads();

        if (tid == 0) {
            double s = 0.0;
            if (idx_i != 0) {
                for (int j = 0; j < cnt; j++) {
                    const float w = s_e[0][j] + s_e[1][j] + s_e[2][j] + s_e[3][j];
                    s += (double)s_d[j] * (double)w;
                }
            }
            g_partial[bi] = s * (double)idx_i;
        }
    } else {
        // ---- fully masked row (frame 49): softmax is uniform 1/TP per head ----
        if (tid < TP) {
            const int j = tid;
            const float* kpj = kpb + (size_t)j * KD;
            float d = 0.0f;
            #pragma unroll
            for (int k = 0; k < KD; k++) d += fabsf(kpj[k] - s_kpi[k]);
            s_d[tid] = d * (float)idx[b * TP + j];
        }
        __syncthreads();
        if (tid == 0) {
            double s = 0.0;
            if (idx_i != 0) {
                for (int j = 0; j < TP; j++) s += (double)s_d[j];
            }
            g_partial[bi] = s * (double)idx_i * ((double)NH / (double)TP);
        }
    }
}

__global__ void finalize_kernel(const int* __restrict__ idx, float* __restrict__ out)
{
    __shared__ double sh[256];
    const int tid = threadIdx.x;

    // sum partials (fixed-order tree -> deterministic)
    double s = 0.0;
    for (int k = tid; k < BSZ * TP; k += 256) s += g_partial[k];
    sh[tid] = s;
    __syncthreads();
    for (int off = 128; off > 0; off >>= 1) {
        if (tid < off) sh[tid] += sh[tid + off];
        __syncthreads();
    }
    const double num = sh[0];
    __syncthreads();

    // den = 1 + NH * sum_b (sum_i idx)^2   (integer-exact per batch)
    double d = 0.0;
    if (tid < BSZ) {
        long long si = 0;
        for (int i = 0; i < TP; i++) si += idx[tid * TP + i];
        d = (double)si * (double)si;
    }
    sh[tid] = d;
    __syncthreads();
    for (int off = 128; off > 0; off >>= 1) {
        if (tid < off) sh[tid] += sh[tid + off];
        __syncthreads();
    }
    if (tid == 0) {
        const double den = 1.0 + (double)NH * sh[0];
        out[0] = (float)(num / den);
    }
}

extern "C" void kernel_launch(void* const* d_in, const int* in_sizes, int n_in,
                              void* d_out, int out_size)
{
    const int*   idx  = (const int*)  d_in[0];  // (32, 150) int32
    // d_in[1] = idx_mask (unused), d_in[2] = idx_kp (unused)
    const float* kp   = (const float*)d_in[3];  // (32, 150, 44, 2) f32
    const float* attn = (const float*)d_in[4];  // (32, 4, 150, 150) f32
    float* out = (float*)d_out;

    smooth_row_kernel<<<BSZ * TP, 160>>>(idx, kp, attn);
    finalize_kernel<<<1, 256>>>(idx, out);
}

// round 2
// speedup vs baseline: 1.4597x; 1.4597x over previous
#include <cuda_runtime.h>
#include <math.h>

#define BSZ 32
#define TT  50
#define PP  3
#define TP  150      // TT*PP
#define NH  4
#define KD  88       // 44 keypoints * 2 coords

// Scratch: per-(b,i) partial sums (device global — no allocation allowed)
__device__ double g_partial[BSZ * TP];

// One block per (b, i) row. blockDim = 160.
__global__ void smooth_row_kernel(const int* __restrict__ idx,
                                  const float* __restrict__ kp,
                                  const float* __restrict__ attn)
{
    const int bi  = blockIdx.x;
    const int b   = bi / TP;
    const int i   = bi % TP;
    const int tid = threadIdx.x;

    __shared__ float s_kpi[KD];
    __shared__ float s_d[TP];       // d(i,j) * idx_j
    __shared__ float s_e[NH][9];    // per-head normalized softmax weights (allowed cols)

    const float* kpb = kp + (size_t)b * TP * KD;
    const int idx_i  = idx[b * TP + i];

    if (tid < KD) s_kpi[tid] = kpb[(size_t)i * KD + tid];
    __syncthreads();

    const int fi = i / PP;

    if (fi < TT - 1) {
        // ---- sparse row: allowed frames [max(fi-1,1)-? ] per mask construction ----
        const int lo  = (fi - 1 > 0) ? (fi - 1) : 0;
        const int hi  = (fi + 1 < TT - 2) ? (fi + 1) : (TT - 2);
        const int jlo = lo * PP;
        const int cnt = (hi - lo + 1) * PP;   // 6 or 9

        if (tid < cnt) {
            const int j = jlo + tid;
            const float* kpj = kpb + (size_t)j * KD;
            float d = 0.0f;
            #pragma unroll
            for (int k = 0; k < KD; k++) d += fabsf(kpj[k] - s_kpi[k]);
            s_d[tid] = d * (float)idx[b * TP + j];
        }
        // heads handled by threads 32..35 (separate warp, runs concurrently)
        if (tid >= 32 && tid < 32 + NH) {
            const int h = tid - 32;
            const float* arow = attn + ((((size_t)b * NH + h) * TP + i) * TP) + jlo;
            float m = -1e30f;
            float a[9];
            for (int j = 0; j < cnt; j++) { a[j] = arow[j]; m = fmaxf(m, a[j]); }
            float Z = 0.0f;
            float e[9];
            for (int j = 0; j < cnt; j++) { e[j] = expf(a[j] - m); Z += e[j]; }
            const float invZ = 1.0f / Z;
            for (int j = 0; j < cnt; j++) s_e[h][j] = e[j] * invZ;
        }
        __syncthreads();

        if (tid == 0) {
            double s = 0.0;
            if (idx_i != 0) {
                for (int j = 0; j < cnt; j++) {
                    const float w = s_e[0][j] + s_e[1][j] + s_e[2][j] + s_e[3][j];
                    s += (double)s_d[j] * (double)w;
                }
            }
            g_partial[bi] = s * (double)idx_i;
        }
    } else {
        // ---- fully masked row (frame 49): softmax is uniform 1/TP per head ----
        if (tid < TP) {
            const int j = tid;
            const float* kpj = kpb + (size_t)j * KD;
            float d = 0.0f;
            #pragma unroll
            for (int k = 0; k < KD; k++) d += fabsf(kpj[k] - s_kpi[k]);
            s_d[tid] = d * (float)idx[b * TP + j];
        }
        __syncthreads();
        if (tid == 0) {
            double s = 0.0;
            if (idx_i != 0) {
                for (int j = 0; j < TP; j++) s += (double)s_d[j];
            }
            g_partial[bi] = s * (double)idx_i * ((double)NH / (double)TP);
        }
    }
}

// 1024 threads, 1 block. Warp-parallel reductions; all loads coalesced + overlapped.
__global__ void finalize_kernel(const int* __restrict__ idx, float* __restrict__ out)
{
    const int tid  = threadIdx.x;
    const int lane = tid & 31;
    const int w    = tid >> 5;      // 32 warps

    __shared__ double sh_num[32];
    __shared__ double sh_den[32];

    // ---- numerator: sum of 4800 partials, coalesced strided reads ----
    double s = 0.0;
    #pragma unroll
    for (int k = tid; k < BSZ * TP; k += 1024) s += g_partial[k];
    #pragma unroll
    for (int o = 16; o > 0; o >>= 1) s += __shfl_down_sync(0xffffffffu, s, o);
    if (lane == 0) sh_num[w] = s;

    // ---- denominator: warp w handles batch w (exact integer sum) ----
    int si = 0;
    #pragma unroll
    for (int k = lane; k < TP; k += 32) si += idx[w * TP + k];
    #pragma unroll
    for (int o = 16; o > 0; o >>= 1) si += __shfl_down_sync(0xffffffffu, si, o);
    if (lane == 0) sh_den[w] = (double)si * (double)si;

    __syncthreads();

    if (w == 0) {
        double n = sh_num[lane];
        double d = sh_den[lane];
        #pragma unroll
        for (int o = 16; o > 0; o >>= 1) {
            n += __shfl_down_sync(0xffffffffu, n, o);
            d += __shfl_down_sync(0xffffffffu, d, o);
        }
        if (lane == 0) {
            const double den = 1.0 + (double)NH * d;
            out[0] = (float)(n / den);
        }
    }
}

extern "C" void kernel_launch(void* const* d_in, const int* in_sizes, int n_in,
                              void* d_out, int out_size)
{
    const int*   idx  = (const int*)  d_in[0];  // (32, 150) int32
    // d_in[1] = idx_mask (unused), d_in[2] = idx_kp (unused)
    const float* kp   = (const float*)d_in[3];  // (32, 150, 44, 2) f32
    const float* attn = (const float*)d_in[4];  // (32, 4, 150, 150) f32
    float* out = (float*)d_out;

    smooth_row_kernel<<<BSZ * TP, 160>>>(idx, kp, attn);
    finalize_kernel<<<1, 1024>>>(idx, out);
}

// round 3
// speedup vs baseline: 1.4744x; 1.0101x over previous
#include <cuda_runtime.h>
#include <math.h>

#define BSZ 32
#define TT  50
#define PP  3
#define TP  150      // TT*PP
#define NH  4
#define KD  88       // 44 keypoints * 2 coords
#define NBLK (BSZ * TP)
#define NTHR 320     // 10 warps

__device__ double g_partial[NBLK];
__device__ int    g_count = 0;   // last-block ticket; reset by last block each call

// full-warp L1 distance over 88 floats; result valid on lane 0
__device__ __forceinline__ float warp_l1(const float* __restrict__ kpj,
                                         const float* __restrict__ s_kpi, int lane)
{
    float d = fabsf(kpj[lane]      - s_kpi[lane]) +
              fabsf(kpj[lane + 32] - s_kpi[lane + 32]);
    if (lane < 24) d += fabsf(kpj[lane + 64] - s_kpi[lane + 64]);
    #pragma unroll
    for (int o = 16; o > 0; o >>= 1) d += __shfl_down_sync(0xffffffffu, d, o);
    return d;
}

__global__ void __launch_bounds__(NTHR)
fused_kernel(const int* __restrict__ idx,
             const float* __restrict__ kp,
             const float* __restrict__ attn,
             float* __restrict__ out)
{
    const int bi   = blockIdx.x;
    const int b    = bi / TP;
    const int i    = bi % TP;
    const int tid  = threadIdx.x;
    const int lane = tid & 31;
    const int w    = tid >> 5;          // 0..9

    __shared__ float  s_kpi[KD];
    __shared__ float  s_d[TP];          // d(i,j) * idx_j
    __shared__ float  s_e[NH][9];       // normalized softmax weights
    __shared__ double sh_num[10];
    __shared__ double sh_den[10];
    __shared__ int    s_last;

    const float* kpb   = kp + (size_t)b * TP * KD;
    const int    idx_i = idx[b * TP + i];

    if (tid < KD) s_kpi[tid] = kpb[(size_t)i * KD + tid];
    __syncthreads();

    const int fi = i / PP;
    double part = 0.0;

    if (fi < TT - 1) {
        // allowed frames [max(fi-1,0), min(fi+1,48)]
        const int lo  = (fi - 1 > 0) ? (fi - 1) : 0;
        const int hi  = (fi + 1 < TT - 2) ? (fi + 1) : (TT - 2);
        const int jlo = lo * PP;
        const int cnt = (hi - lo + 1) * PP;     // 6 or 9

        if (w < cnt) {
            const int j = jlo + w;
            const float d = warp_l1(kpb + (size_t)j * KD, s_kpi, lane);
            if (lane == 0) s_d[w] = d * (float)idx[b * TP + j];
        }
        if (w == 9 && lane < NH) {
            const int h = lane;
            const float* arow = attn + ((((size_t)b * NH + h) * TP + i) * TP) + jlo;
            float a[9], m = -1e30f;
            for (int j = 0; j < cnt; j++) { a[j] = arow[j]; m = fmaxf(m, a[j]); }
            float e[9], Z = 0.0f;
            for (int j = 0; j < cnt; j++) { e[j] = expf(a[j] - m); Z += e[j]; }
            const float invZ = 1.0f / Z;
            for (int j = 0; j < cnt; j++) s_e[h][j] = e[j] * invZ;
        }
        __syncthreads();

        if (tid == 0 && idx_i != 0) {
            double s = 0.0;
            for (int j = 0; j < cnt; j++) {
                const float ww = s_e[0][j] + s_e[1][j] + s_e[2][j] + s_e[3][j];
                s += (double)s_d[j] * (double)ww;
            }
            part = s * (double)idx_i;
        }
    } else {
        // frame 49: fully masked row -> uniform softmax 1/TP per head
        for (int j = w; j < TP; j += 10) {
            const float d = warp_l1(kpb + (size_t)j * KD, s_kpi, lane);
            if (lane == 0) s_d[j] = d * (float)idx[b * TP + j];
        }
        __syncthreads();
        if (w == 0) {
            double s = 0.0;
            for (int k = lane; k < TP; k += 32) s += (double)s_d[k];
            #pragma unroll
            for (int o = 16; o > 0; o >>= 1) s += __shfl_down_sync(0xffffffffu, s, o);
            if (lane == 0 && idx_i != 0)
                part = s * (double)idx_i * ((double)NH / (double)TP);
        }
    }

    // ---- publish partial, elect last block ----
    if (tid == 0) {
        g_partial[bi] = part;
        __threadfence();
        s_last = (atomicAdd(&g_count, 1) == NBLK - 1);
    }
    __syncthreads();
    if (!s_last) return;
    __threadfence();

    // ---- last block: deterministic final reduction ----
    // numerator: 4800 doubles, coalesced
    double s = 0.0;
    #pragma unroll
    for (int k = tid; k < NBLK; k += NTHR) s += g_partial[k];
    #pragma unroll
    for (int o = 16; o > 0; o >>= 1) s += __shfl_down_sync(0xffffffffu, s, o);
    if (lane == 0) sh_num[w] = s;

    // denominator: warp w handles batches w, w+10, w+20, (w+30)
    double dsum = 0.0;
    for (int bb = w; bb < BSZ; bb += 10) {
        int si = 0;
        for (int k = lane; k < TP; k += 32) si += idx[bb * TP + k];
        #pragma unroll
        for (int o = 16; o > 0; o >>= 1) si += __shfl_down_sync(0xffffffffu, si, o);
        if (lane == 0) dsum += (double)si * (double)si;
    }
    if (lane == 0) sh_den[w] = dsum;
    __syncthreads();

    if (tid == 0) {
        double num = 0.0, den = 0.0;
        #pragma unroll
        for (int k = 0; k < 10; k++) { num += sh_num[k]; den += sh_den[k]; }
        out[0] = (float)(num / (1.0 + (double)NH * den));
        g_count = 0;                 // reset for next graph replay
        __threadfence();
    }
}

extern "C" void kernel_launch(void* const* d_in, const int* in_sizes, int n_in,
                              void* d_out, int out_size)
{
    const int*   idx  = (const int*)  d_in[0];  // (32, 150) int32
    // d_in[1] = idx_mask (unused), d_in[2] = idx_kp (unused)
    const float* kp   = (const float*)d_in[3];  // (32, 150, 44, 2) f32
    const float* attn = (const float*)d_in[4];  // (32, 4, 150, 150) f32
    float* out = (float*)d_out;

    fused_kernel<<<NBLK, NTHR>>>(idx, kp, attn, out);
}

// round 4
// speedup vs baseline: 2.7196x; 1.8446x over previous
#include <cuda_runtime.h>
#include <math.h>

#define BSZ 32
#define TT  50
#define PP  3
#define TP  150      // TT*PP
#define NH  4
#define KD  88       // 44 keypoints * 2 coords
#define CHK 4        // row-chunks per batch
#define RPC 38       // rows per chunk (last chunk: 36)
#define NBLK (BSZ * CHK)   // 128 blocks
#define NTHR 512

__device__ double g_num[NBLK];
__device__ double g_den[BSZ];
__device__ int    g_count = 0;   // ticket; reset by last block every call

// L1 distance between kp rows i and j (per-thread, float4 loads, 4 accumulators)
__device__ __forceinline__ float l1_dist(const float* __restrict__ kpb, int i, int j)
{
    const float4* pi = (const float4*)(kpb + (size_t)i * KD);
    const float4* pj = (const float4*)(kpb + (size_t)j * KD);
    float a0 = 0.f, a1 = 0.f, a2 = 0.f, a3 = 0.f;
    #pragma unroll
    for (int k = 0; k < KD / 4; k++) {
        const float4 x = pi[k], y = pj[k];
        a0 += fabsf(x.x - y.x);
        a1 += fabsf(x.y - y.y);
        a2 += fabsf(x.z - y.z);
        a3 += fabsf(x.w - y.w);
    }
    return (a0 + a1) + (a2 + a3);
}

__global__ void __launch_bounds__(NTHR)
fused_kernel(const int* __restrict__ idx,
             const float* __restrict__ kp,
             const float* __restrict__ attn,
             float* __restrict__ out)
{
    const int blk  = blockIdx.x;
    const int b    = blk / CHK;
    const int c    = blk % CHK;
    const int row0 = c * RPC;
    const int nrows = (row0 + RPC <= TP) ? RPC : (TP - row0);   // 38,38,38,36
    const int tid  = threadIdx.x;
    const int lane = tid & 31;
    const int w    = tid >> 5;    // 0..15

    __shared__ float  s_d[RPC * 9];        // d(i,j)*idx_j for sparse rows
    __shared__ float  s_e[RPC][NH][9];     // per-head softmax weights
    __shared__ float  s_dfull[PP][TP];     // frame-49 rows (chunk 3 only)
    __shared__ float  s_part[RPC > 32 ? 64 : 32];
    __shared__ float  s_pfull[PP];
    __shared__ double sh_n[NTHR / 32];
    __shared__ double sh_dn[NTHR / 32];
    __shared__ int    s_last;

    const float* kpb  = kp  + (size_t)b * TP * KD;
    const int*   idxb = idx + b * TP;

    // zero pad for block reduce
    if (tid < 64) s_part[tid] = 0.f;

    // ---- Phase A: sparse-row distances (thread per (row, col-slot)) ----
    for (int t = tid; t < nrows * 9; t += NTHR) {
        const int r  = t / 9;
        const int jp = t % 9;
        const int i  = row0 + r;
        const int fi = i / PP;
        if (fi >= TT - 1) continue;                 // frame-49 rows handled below
        const int lo  = (fi - 1 > 0) ? (fi - 1) : 0;
        const int hi  = (fi + 1 < TT - 2) ? (fi + 1) : (TT - 2);
        const int cnt = (hi - lo + 1) * PP;         // 6 or 9
        if (jp >= cnt) continue;
        const int j = lo * PP + jp;
        const float d = (j == i) ? 0.f : l1_dist(kpb, i, j);
        s_d[r * 9 + jp] = d * (float)idxb[j];
    }

    // ---- Phase A2: frame-49 rows, full 150 columns (chunk 3 only) ----
    if (c == CHK - 1) {
        for (int t = tid; t < PP * TP; t += NTHR) {
            const int fr = t / TP;
            const int j  = t % TP;
            const int i  = TP - PP + fr;            // 147..149
            const float d = (j == i) ? 0.f : l1_dist(kpb, i, j);
            s_dfull[fr][j] = d * (float)idxb[j];
        }
    }

    // ---- Phase B: softmax per (row, head) over allowed columns ----
    for (int t = tid; t < nrows * NH; t += NTHR) {
        const int r = t / NH;
        const int h = t % NH;
        const int i  = row0 + r;
        const int fi = i / PP;
        if (fi >= TT - 1) continue;
        const int lo  = (fi - 1 > 0) ? (fi - 1) : 0;
        const int hi  = (fi + 1 < TT - 2) ? (fi + 1) : (TT - 2);
        const int cnt = (hi - lo + 1) * PP;
        const int jlo = lo * PP;
        const float* arow = attn + ((((size_t)b * NH + h) * TP + i) * TP) + jlo;
        float a[9], m = -1e30f;
        for (int jj = 0; jj < cnt; jj++) { a[jj] = arow[jj]; m = fmaxf(m, a[jj]); }
        float e[9], Z = 0.f;
        for (int jj = 0; jj < cnt; jj++) { e[jj] = expf(a[jj] - m); Z += e[jj]; }
        const float invZ = 1.f / Z;
        for (int jj = 0; jj < cnt; jj++) s_e[r][h][jj] = e[jj] * invZ;
    }

    __syncthreads();

    // ---- Phase C: per-row dots ----
    if (tid < nrows) {
        const int r  = tid;
        const int i  = row0 + r;
        const int fi = i / PP;
        if (fi < TT - 1) {
            const int lo  = (fi - 1 > 0) ? (fi - 1) : 0;
            const int hi  = (fi + 1 < TT - 2) ? (fi + 1) : (TT - 2);
            const int cnt = (hi - lo + 1) * PP;
            float s = 0.f;
            for (int jj = 0; jj < cnt; jj++) {
                const float ww = (s_e[r][0][jj] + s_e[r][1][jj]) +
                                 (s_e[r][2][jj] + s_e[r][3][jj]);
                s += s_d[r * 9 + jj] * ww;
            }
            s_part[r] = s * (float)idxb[i];
        }
        // frame-49 rows: s_part stays 0 (handled by warps 13..15)
    }

    // frame-49 full-row dots: warps 13,14,15 (threads 416..511, no overlap with above)
    if (c == CHK - 1 && w >= 13) {
        const int fr = w - 13;
        float s = 0.f;
        for (int k = lane; k < TP; k += 32) s += s_dfull[fr][k];
        #pragma unroll
        for (int o = 16; o > 0; o >>= 1) s += __shfl_down_sync(0xffffffffu, s, o);
        if (lane == 0)
            s_pfull[fr] = s * (float)idxb[TP - PP + fr] * ((float)NH / (float)TP);
    }

    // ---- Phase D: denominator (one block per batch: c==0, warp 12) ----
    if (c == 0 && w == 12) {
        int si = 0;
        for (int k = lane; k < TP; k += 32) si += idxb[k];
        #pragma unroll
        for (int o = 16; o > 0; o >>= 1) si += __shfl_down_sync(0xffffffffu, si, o);
        if (lane == 0) {
            g_den[b] = (double)si * (double)si;
            __threadfence();
        }
    }

    __syncthreads();

    // ---- Phase E: block reduce + publish ----
    if (w == 0) {
        float s = s_part[lane] + s_part[lane + 32];
        #pragma unroll
        for (int o = 16; o > 0; o >>= 1) s += __shfl_down_sync(0xffffffffu, s, o);
        if (lane == 0) {
            double tot = (double)s;
            if (c == CHK - 1) tot += (double)s_pfull[0] + (double)s_pfull[1] + (double)s_pfull[2];
            g_num[blk] = tot;
            __threadfence();
            s_last = (atomicAdd(&g_count, 1) == NBLK - 1);
        }
    }
    __syncthreads();
    if (!s_last) return;
    __threadfence();

    // ---- last block: final deterministic reduction ----
    double n = (tid < NBLK) ? g_num[tid] : 0.0;
    double d = (tid < BSZ)  ? g_den[tid] : 0.0;
    #pragma unroll
    for (int o = 16; o > 0; o >>= 1) {
        n += __shfl_down_sync(0xffffffffu, n, o);
        d += __shfl_down_sync(0xffffffffu, d, o);
    }
    if (lane == 0) { sh_n[w] = n; sh_dn[w] = d; }
    __syncthreads();
    if (tid == 0) {
        double num = 0.0, den = 0.0;
        #pragma unroll
        for (int k = 0; k < NTHR / 32; k++) { num += sh_n[k]; den += sh_dn[k]; }
        out[0] = (float)(num / (1.0 + (double)NH * den));
        g_count = 0;               // reset for next graph replay
        __threadfence();
    }
}

extern "C" void kernel_launch(void* const* d_in, const int* in_sizes, int n_in,
                              void* d_out, int out_size)
{
    const int*   idx  = (const int*)  d_in[0];  // (32, 150) int32
    // d_in[1] = idx_mask (unused), d_in[2] = idx_kp (unused)
    const float* kp   = (const float*)d_in[3];  // (32, 150, 44, 2) f32
    const float* attn = (const float*)d_in[4];  // (32, 4, 150, 150) f32
    float* out = (float*)d_out;

    fused_kernel<<<NBLK, NTHR>>>(idx, kp, attn, out);
}

// round 5
// speedup vs baseline: 2.7855x; 1.0242x over previous
#include <cuda_runtime.h>
#include <math.h>

#define BSZ 32
#define TT  50
#define PP  3
#define TP  150      // TT*PP
#define NH  4
#define KD  88       // 44 keypoints * 2 coords
#define CHK 4        // row-chunks per batch
#define RPC 38       // rows per chunk (last chunk: 36)
#define NBLK (BSZ * CHK)   // 128 blocks
#define NTHR 512
#define WROWS 48     // max kp window rows per chunk

__device__ double g_num[NBLK];
__device__ double g_den[BSZ];
__device__ int    g_count = 0;   // ticket; reset by last block every call

// L1 distance from GLOBAL kp (frame-49 rows only)
__device__ __forceinline__ float l1_dist_g(const float* __restrict__ kpb, int i, int j)
{
    const float4* pi = (const float4*)(kpb + (size_t)i * KD);
    const float4* pj = (const float4*)(kpb + (size_t)j * KD);
    float a0 = 0.f, a1 = 0.f, a2 = 0.f, a3 = 0.f;
    #pragma unroll
    for (int k = 0; k < KD / 4; k++) {
        const float4 x = pi[k], y = pj[k];
        a0 += fabsf(x.x - y.x);
        a1 += fabsf(x.y - y.y);
        a2 += fabsf(x.z - y.z);
        a3 += fabsf(x.w - y.w);
    }
    return (a0 + a1) + (a2 + a3);
}

__global__ void __launch_bounds__(NTHR)
fused_kernel(const int* __restrict__ idx,
             const float* __restrict__ kp,
             const float* __restrict__ attn,
             float* __restrict__ out)
{
    const int blk   = blockIdx.x;
    const int b     = blk / CHK;
    const int c     = blk % CHK;
    const int row0  = c * RPC;
    const int nrows = (row0 + RPC <= TP) ? RPC : (TP - row0);   // 38,38,38,36
    const int tid   = threadIdx.x;
    const int lane  = tid & 31;
    const int w     = tid >> 5;    // 0..15

    __shared__ float  s_kpw[WROWS * KD];    // kp frame window      (16.9 KB)
    __shared__ float  s_a[RPC][NH][9];      // attn -> softmax (in place)
    __shared__ float  s_d[RPC][9];          // d(i,j)*idx_j
    __shared__ float  s_dfull[PP][TP];      // frame-49 rows (chunk 3)
    __shared__ int    s_idx[TP];
    __shared__ float  s_part[64];
    __shared__ float  s_pfull[PP];
    __shared__ double sh_n[NTHR / 32];
    __shared__ double sh_dn[NTHR / 32];
    __shared__ int    s_last;

    const float* kpb  = kp  + (size_t)b * TP * KD;
    const int*   idxb = idx + b * TP;

    // kp window: frames [f_first-1, min(f_last+1, 48)]
    const int f_first = row0 / PP;
    int f_last = (row0 + nrows - 1) / PP;
    if (f_last > TT - 2) f_last = TT - 2;     // frame-49 rows use global path
    const int w_f0 = (f_first - 1 > 0) ? (f_first - 1) : 0;
    const int w_f1 = (f_last + 1 < TT - 2) ? (f_last + 1) : (TT - 2);
    const int w_r0 = w_f0 * PP;
    const int w_n  = (w_f1 - w_f0 + 1) * PP;  // <= 48 rows

    // ---- Phase 0: issue all global loads early (high MLP) ----
    // attn slices -> s_a (always 9 wide; jlo+8 <= 149 guaranteed)
    for (int t = tid; t < nrows * NH * 9; t += NTHR) {
        const int jj = t % 9;
        const int rh = t / 9;
        const int h  = rh % NH;
        const int r  = rh / NH;
        const int i  = row0 + r;
        const int fi = i / PP;
        if (fi >= TT - 1) continue;
        const int lo  = (fi - 1 > 0) ? (fi - 1) : 0;
        const int jlo = lo * PP;
        s_a[r][h][jj] = attn[((((size_t)b * NH + h) * TP + i) * TP) + jlo + jj];
    }
    // kp window -> s_kpw (coalesced float4)
    {
        const float4* src = (const float4*)(kpb + (size_t)w_r0 * KD);
        float4*       dst = (float4*)s_kpw;
        const int nf4 = w_n * (KD / 4);
        for (int t = tid; t < nf4; t += NTHR) dst[t] = src[t];
    }
    if (tid < TP) s_idx[tid] = idxb[tid];
    if (tid < 64) s_part[tid] = 0.f;
    __syncthreads();

    // ---- Phase 1a: sparse distances from smem ----
    for (int t = tid; t < nrows * 9; t += NTHR) {
        const int r  = t / 9;
        const int jp = t % 9;
        const int i  = row0 + r;
        const int fi = i / PP;
        if (fi >= TT - 1) continue;
        const int lo  = (fi - 1 > 0) ? (fi - 1) : 0;
        const int hi  = (fi + 1 < TT - 2) ? (fi + 1) : (TT - 2);
        const int cnt = (hi - lo + 1) * PP;
        if (jp >= cnt) { s_d[r][jp] = 0.f; continue; }
        const int j = lo * PP + jp;
        const float4* pi = (const float4*)(s_kpw + (i - w_r0) * KD);
        const float4* pj = (const float4*)(s_kpw + (j - w_r0) * KD);
        float a0 = 0.f, a1 = 0.f, a2 = 0.f, a3 = 0.f;
        #pragma unroll
        for (int k = 0; k < KD / 4; k++) {
            const float4 x = pi[k], y = pj[k];
            a0 += fabsf(x.x - y.x);
            a1 += fabsf(x.y - y.y);
            a2 += fabsf(x.z - y.z);
            a3 += fabsf(x.w - y.w);
        }
        s_d[r][jp] = ((a0 + a1) + (a2 + a3)) * (float)s_idx[j];
    }

    // ---- Phase 1b: frame-49 full rows from global (chunk 3 only) ----
    if (c == CHK - 1) {
        for (int t = tid; t < PP * TP; t += NTHR) {
            const int fr = t / TP;
            const int j  = t % TP;
            const int i  = TP - PP + fr;            // 147..149
            s_dfull[fr][j] = l1_dist_g(kpb, i, j) * (float)s_idx[j];
        }
    }

    // ---- Phase 1c: softmax in place (fully unrolled, predicated) ----
    for (int t = tid; t < nrows * NH; t += NTHR) {
        const int r  = t / NH;
        const int h  = t % NH;
        const int i  = row0 + r;
        const int fi = i / PP;
        if (fi >= TT - 1) continue;
        const int lo  = (fi - 1 > 0) ? (fi - 1) : 0;
        const int hi  = (fi + 1 < TT - 2) ? (fi + 1) : (TT - 2);
        const int cnt = (hi - lo + 1) * PP;
        float a[9];
        #pragma unroll
        for (int jj = 0; jj < 9; jj++) a[jj] = s_a[r][h][jj];
        float m = -1e30f;
        #pragma unroll
        for (int jj = 0; jj < 9; jj++) if (jj < cnt) m = fmaxf(m, a[jj]);
        float e[9], Z = 0.f;
        #pragma unroll
        for (int jj = 0; jj < 9; jj++) {
            e[jj] = (jj < cnt) ? expf(a[jj] - m) : 0.f;
            Z += e[jj];
        }
        const float invZ = 1.f / Z;
        #pragma unroll
        for (int jj = 0; jj < 9; jj++) s_a[r][h][jj] = e[jj] * invZ;
    }

    __syncthreads();

    // ---- Phase 2: per-row dots ----
    if (tid < nrows) {
        const int r  = tid;
        const int i  = row0 + r;
        const int fi = i / PP;
        if (fi < TT - 1) {
            float s = 0.f;
            #pragma unroll
            for (int jj = 0; jj < 9; jj++) {
                const float ww = (s_a[r][0][jj] + s_a[r][1][jj]) +
                                 (s_a[r][2][jj] + s_a[r][3][jj]);
                s += s_d[r][jj] * ww;
            }
            s_part[r] = s * (float)s_idx[i];
        }
    }

    // frame-49 full-row dots: warps 13..15 (no overlap with tid<38)
    if (c == CHK - 1 && w >= 13) {
        const int fr = w - 13;
        float s = 0.f;
        for (int k = lane; k < TP; k += 32) s += s_dfull[fr][k];
        #pragma unroll
        for (int o = 16; o > 0; o >>= 1) s += __shfl_down_sync(0xffffffffu, s, o);
        if (lane == 0)
            s_pfull[fr] = s * (float)s_idx[TP - PP + fr] * ((float)NH / (float)TP);
    }

    // denominator (one block per batch)
    if (c == 0 && w == 12) {
        int si = 0;
        for (int k = lane; k < TP; k += 32) si += s_idx[k];
        #pragma unroll
        for (int o = 16; o > 0; o >>= 1) si += __shfl_down_sync(0xffffffffu, si, o);
        if (lane == 0) {
            g_den[b] = (double)si * (double)si;
            __threadfence();
        }
    }

    __syncthreads();

    // ---- Phase 3: block reduce + publish ----
    if (w == 0) {
        float s = s_part[lane] + s_part[lane + 32];
        #pragma unroll
        for (int o = 16; o > 0; o >>= 1) s += __shfl_down_sync(0xffffffffu, s, o);
        if (lane == 0) {
            double tot = (double)s;
            if (c == CHK - 1)
                tot += (double)s_pfull[0] + (double)s_pfull[1] + (double)s_pfull[2];
            g_num[blk] = tot;
            __threadfence();
            s_last = (atomicAdd(&g_count, 1) == NBLK - 1);
        }
    }
    __syncthreads();
    if (!s_last) return;
    __threadfence();

    // ---- last block: final deterministic reduction ----
    double n = (tid < NBLK) ? g_num[tid] : 0.0;
    double d = (tid < BSZ)  ? g_den[tid] : 0.0;
    #pragma unroll
    for (int o = 16; o > 0; o >>= 1) {
        n += __shfl_down_sync(0xffffffffu, n, o);
        d += __shfl_down_sync(0xffffffffu, d, o);
    }
    if (lane == 0) { sh_n[w] = n; sh_dn[w] = d; }
    __syncthreads();
    if (tid == 0) {
        double num = 0.0, den = 0.0;
        #pragma unroll
        for (int k = 0; k < NTHR / 32; k++) { num += sh_n[k]; den += sh_dn[k]; }
        out[0] = (float)(num / (1.0 + (double)NH * den));
        g_count = 0;               // reset for next graph replay
        __threadfence();
    }
}

extern "C" void kernel_launch(void* const* d_in, const int* in_sizes, int n_in,
                              void* d_out, int out_size)
{
    const int*   idx  = (const int*)  d_in[0];  // (32, 150) int32
    // d_in[1] = idx_mask (unused), d_in[2] = idx_kp (unused)
    const float* kp   = (const float*)d_in[3];  // (32, 150, 44, 2) f32
    const float* attn = (const float*)d_in[4];  // (32, 4, 150, 150) f32
    float* out = (float*)d_out;

    fused_kernel<<<NBLK, NTHR>>>(idx, kp, attn, out);
}

// round 6
// speedup vs baseline: 3.4773x; 1.2484x over previous
#include <cuda_runtime.h>
#include <math.h>

#define BSZ 32
#define TT  50
#define PP  3
#define TP  150      // TT*PP
#define NH  4
#define KD  88       // 44 keypoints * 2 coords
#define KP4 (KD / 4) // 22 float4 per row
#define KPAD 92      // padded smem row stride (floats): 92 % 32 = 28 -> conflict-free
#define KPAD4 (KPAD / 4)
#define CHK 4
#define RPC 38       // rows per chunk (last: 36)
#define NBLK (BSZ * CHK)   // 128
#define NTHR 512
#define WROWS 48

__device__ double g_num[NBLK];
__device__ double g_den[BSZ];
__device__ int    g_count = 0;   // ticket; reset by last block every call

// L1 distance between two padded smem rows
__device__ __forceinline__ float l1_dist_s(const float* __restrict__ pi_,
                                           const float* __restrict__ pj_)
{
    const float4* pi = (const float4*)pi_;
    const float4* pj = (const float4*)pj_;
    float a0 = 0.f, a1 = 0.f, a2 = 0.f, a3 = 0.f;
    #pragma unroll
    for (int k = 0; k < KP4; k++) {
        const float4 x = pi[k], y = pj[k];
        a0 += fabsf(x.x - y.x);
        a1 += fabsf(x.y - y.y);
        a2 += fabsf(x.z - y.z);
        a3 += fabsf(x.w - y.w);
    }
    return (a0 + a1) + (a2 + a3);
}

__global__ void __launch_bounds__(NTHR)
fused_kernel(const int* __restrict__ idx,
             const float* __restrict__ kp,
             const float* __restrict__ attn,
             float* __restrict__ out)
{
    const int blk   = blockIdx.x;
    const int b     = blk / CHK;
    const int c     = blk % CHK;
    const int row0  = c * RPC;
    const int nrows = (row0 + RPC <= TP) ? RPC : (TP - row0);   // 38,38,38,36
    const int tid   = threadIdx.x;
    const int lane  = tid & 31;
    const int w     = tid >> 5;

    __shared__ float  s_kpw[WROWS * KPAD];   // padded kp frame window (17.7 KB)
    __shared__ float  s_kpd[PP * KPAD];      // dense rows 147..149     (1.1 KB)
    __shared__ float  s_a[RPC][NH][9];       // attn -> softmax in place
    __shared__ float  s_d[RPC][9];           // d(i,j)*idx_j (sparse)
    __shared__ float  s_dd[PP][RPC];         // dense slice d*idx_j
    __shared__ int    s_idx[TP];
    __shared__ float  s_part[64];
    __shared__ float  s_pd[PP];              // dense partial sums
    __shared__ double sh_n[NTHR / 32];
    __shared__ double sh_dn[NTHR / 32];
    __shared__ int    s_last;

    const float* kpb  = kp  + (size_t)b * TP * KD;
    const int*   idxb = idx + b * TP;

    // kp window frames
    const int f_first = row0 / PP;
    int f_last = (row0 + nrows - 1) / PP;
    if (f_last > TT - 2) f_last = TT - 2;
    const int w_f0 = (f_first - 1 > 0) ? (f_first - 1) : 0;
    const int w_f1 = (f_last + 1 < TT - 2) ? (f_last + 1) : (TT - 2);
    const int w_r0 = w_f0 * PP;
    const int w_n  = (w_f1 - w_f0 + 1) * PP;       // <= 48

    const int nj = (c < CHK - 1) ? RPC : (TP - row0);   // dense col slice width
    const int j0 = c * RPC;

    // ---- Phase 0: all global loads, issued early ----
    for (int t = tid; t < nrows * NH * 9; t += NTHR) {
        const int jj = t % 9;
        const int rh = t / 9;
        const int h  = rh % NH;
        const int r  = rh / NH;
        const int i  = row0 + r;
        const int fi = i / PP;
        if (fi >= TT - 1) continue;
        const int lo = (fi - 1 > 0) ? (fi - 1) : 0;
        s_a[r][h][jj] = attn[((((size_t)b * NH + h) * TP + i) * TP) + lo * PP + jj];
    }
    {   // window rows, padded copy
        const float4* src = (const float4*)(kpb + (size_t)w_r0 * KD);
        float4*       dst = (float4*)s_kpw;
        for (int t = tid; t < w_n * KP4; t += NTHR) {
            const int r = t / KP4, k = t % KP4;
            dst[r * KPAD4 + k] = src[t];
        }
    }
    {   // dense rows 147..149, padded copy
        const float4* srcd = (const float4*)(kpb + (size_t)(TP - PP) * KD);
        float4*       dstd = (float4*)s_kpd;
        if (tid < PP * KP4) {
            const int r = tid / KP4, k = tid % KP4;
            dstd[r * KPAD4 + k] = srcd[tid];
        }
    }
    if (tid < TP) s_idx[tid] = idxb[tid];
    if (tid < 64) s_part[tid] = 0.f;
    __syncthreads();

    // ---- Phase 1a: sparse distances (threads 0..nrows*9-1) ----
    if (tid < nrows * 9) {
        const int r  = tid / 9;
        const int jp = tid % 9;
        const int i  = row0 + r;
        const int fi = i / PP;
        float v = 0.f;
        if (fi < TT - 1) {
            const int lo  = (fi - 1 > 0) ? (fi - 1) : 0;
            const int hi  = (fi + 1 < TT - 2) ? (fi + 1) : (TT - 2);
            const int cnt = (hi - lo + 1) * PP;
            if (jp < cnt) {
                const int j = lo * PP + jp;
                const float d = l1_dist_s(s_kpw + (i - w_r0) * KPAD,
                                          s_kpw + (j - w_r0) * KPAD);
                v = d * (float)s_idx[j];
            }
        }
        s_d[r][jp] = v;
    }

    // ---- Phase 1b: dense slice (next 3*nj threads) ----
    {
        const int t = tid - nrows * 9;
        if (t >= 0 && t < PP * nj) {
            const int fr = t / nj;
            const int jj = t % nj;
            const int j  = j0 + jj;
            const float* pj = (j >= TP - PP) ? (s_kpd + (j - (TP - PP)) * KPAD)
                                             : (s_kpw + (j - w_r0) * KPAD);
            const float d = l1_dist_s(s_kpd + fr * KPAD, pj);
            s_dd[fr][jj] = d * (float)s_idx[j];
        }
    }

    // ---- Phase 1c: softmax in place (strided over all threads) ----
    for (int t = tid; t < nrows * NH; t += NTHR) {
        const int r  = t / NH;
        const int h  = t % NH;
        const int i  = row0 + r;
        const int fi = i / PP;
        if (fi >= TT - 1) continue;
        const int lo  = (fi - 1 > 0) ? (fi - 1) : 0;
        const int hi  = (fi + 1 < TT - 2) ? (fi + 1) : (TT - 2);
        const int cnt = (hi - lo + 1) * PP;
        float a[9];
        #pragma unroll
        for (int jj = 0; jj < 9; jj++) a[jj] = s_a[r][h][jj];
        float m = -1e30f;
        #pragma unroll
        for (int jj = 0; jj < 9; jj++) if (jj < cnt) m = fmaxf(m, a[jj]);
        float e[9], Z = 0.f;
        #pragma unroll
        for (int jj = 0; jj < 9; jj++) { e[jj] = (jj < cnt) ? expf(a[jj] - m) : 0.f; Z += e[jj]; }
        const float invZ = 1.f / Z;
        #pragma unroll
        for (int jj = 0; jj < 9; jj++) s_a[r][h][jj] = e[jj] * invZ;
    }

    __syncthreads();

    // ---- Phase 2: per-row dots ----
    if (tid < nrows) {
        const int r  = tid;
        const int i  = row0 + r;
        const int fi = i / PP;
        if (fi < TT - 1) {
            float s = 0.f;
            #pragma unroll
            for (int jj = 0; jj < 9; jj++) {
                const float ww = (s_a[r][0][jj] + s_a[r][1][jj]) +
                                 (s_a[r][2][jj] + s_a[r][3][jj]);
                s += s_d[r][jj] * ww;
            }
            s_part[r] = s * (float)s_idx[i];
        }
    }

    // dense slice row sums: warps 13..15
    if (w >= 13) {
        const int fr = w - 13;
        float s = (lane < nj) ? s_dd[fr][lane] : 0.f;
        if (lane + 32 < nj) s += s_dd[fr][lane + 32];
        #pragma unroll
        for (int o = 16; o > 0; o >>= 1) s += __shfl_down_sync(0xffffffffu, s, o);
        if (lane == 0)
            s_pd[fr] = s * (float)s_idx[TP - PP + fr] * ((float)NH / (float)TP);
    }

    // denominator: one block per batch
    if (c == 0 && w == 12) {
        int si = 0;
        for (int k = lane; k < TP; k += 32) si += s_idx[k];
        #pragma unroll
        for (int o = 16; o > 0; o >>= 1) si += __shfl_down_sync(0xffffffffu, si, o);
        if (lane == 0) {
            g_den[b] = (double)si * (double)si;
            __threadfence();
        }
    }

    __syncthreads();

    // ---- Phase 3: block reduce + publish ----
    if (w == 0) {
        float s = s_part[lane] + s_part[lane + 32];
        #pragma unroll
        for (int o = 16; o > 0; o >>= 1) s += __shfl_down_sync(0xffffffffu, s, o);
        if (lane == 0) {
            double tot = (double)s +
                         (double)s_pd[0] + (double)s_pd[1] + (double)s_pd[2];
            g_num[blk] = tot;
            __threadfence();
            s_last = (atomicAdd(&g_count, 1) == NBLK - 1);
        }
    }
    __syncthreads();
    if (!s_last) return;
    __threadfence();

    // ---- last block: final deterministic reduction ----
    double n = (tid < NBLK) ? g_num[tid] : 0.0;
    double d = (tid < BSZ)  ? g_den[tid] : 0.0;
    #pragma unroll
    for (int o = 16; o > 0; o >>= 1) {
        n += __shfl_down_sync(0xffffffffu, n, o);
        d += __shfl_down_sync(0xffffffffu, d, o);
    }
    if (lane == 0) { sh_n[w] = n; sh_dn[w] = d; }
    __syncthreads();
    if (tid == 0) {
        double num = 0.0, den = 0.0;
        #pragma unroll
        for (int k = 0; k < NTHR / 32; k++) { num += sh_n[k]; den += sh_dn[k]; }
        out[0] = (float)(num / (1.0 + (double)NH * den));
        g_count = 0;
        __threadfence();
    }
}

extern "C" void kernel_launch(void* const* d_in, const int* in_sizes, int n_in,
                              void* d_out, int out_size)
{
    const int*   idx  = (const int*)  d_in[0];  // (32, 150) int32
    const float* kp   = (const float*)d_in[3];  // (32, 150, 44, 2) f32
    const float* attn = (const float*)d_in[4];  // (32, 4, 150, 150) f32
    float* out = (float*)d_out;

    fused_kernel<<<NBLK, NTHR>>>(idx, kp, attn, out);
}